// round 6
// baseline (speedup 1.0000x reference)
#include <cuda_runtime.h>

namespace {
constexpr int kB = 2, kNP = 4, kN = 64, kP = 24, kCin = 16, kC = 32, kT = 96;
constexpr int kRows = kB * kNP * kN * kP;                                // 12288
constexpr long long kAttElems = (long long)kB * kN * kN * kT * kC;       // 25165824
constexpr int kPad = 36;          // smem row stride (floats), 16B-aligned
constexpr float kLog2e = 1.4426950408889634f;
}

__device__ float g_h[kRows * kC];   // h = x @ W, (B*6144, 32) row-major

__device__ __forceinline__ float ex2f(float x) {
    float r; asm("ex2.approx.f32 %0, %1;" : "=f"(r) : "f"(x)); return r;
}
__device__ __forceinline__ float rcpf(float x) {
    float r; asm("rcp.approx.f32 %0, %1;" : "=f"(r) : "f"(x)); return r;
}

// Kernel 1: h = x @ W. One thread = one row x 4-channel quad.
__global__ void h_kernel(const float* __restrict__ x, const float* __restrict__ W) {
    int gid = blockIdx.x * 256 + threadIdx.x;   // 98304 threads
    int q = gid & 7;                            // channel quad (c = 4q..4q+3)
    int row = gid >> 3;
    const float4* xr = (const float4*)(x + row * kCin);
    const float4* Wq = (const float4*)W + q;    // quad of W row k is at k*8+q
    float4 a0 = __ldg(xr), a1 = __ldg(xr + 1), a2 = __ldg(xr + 2), a3 = __ldg(xr + 3);
    float4 acc = make_float4(0.f, 0.f, 0.f, 0.f);
#define FMA4(s, k) { float4 w = __ldg(Wq + (k) * 8); \
    acc.x = fmaf(s, w.x, acc.x); acc.y = fmaf(s, w.y, acc.y); \
    acc.z = fmaf(s, w.z, acc.z); acc.w = fmaf(s, w.w, acc.w); }
    FMA4(a0.x, 0)  FMA4(a0.y, 1)  FMA4(a0.z, 2)  FMA4(a0.w, 3)
    FMA4(a1.x, 4)  FMA4(a1.y, 5)  FMA4(a1.z, 6)  FMA4(a1.w, 7)
    FMA4(a2.x, 8)  FMA4(a2.y, 9)  FMA4(a2.z, 10) FMA4(a2.w, 11)
    FMA4(a3.x, 12) FMA4(a3.y, 13) FMA4(a3.z, 14) FMA4(a3.w, 15)
#undef FMA4
    *(float4*)(g_h + row * kC + q * 4) = acc;
}

// Kernel 2: warp = (b,s,i,p). 4-lane group owns one j (8 j's per iter, 8 iters);
// lane owns 8 scalar channels. adj pre-scaled by log2e so inner op is
// x=hi*hj; m=max(x*A1, x*A2); ex2; 2-stage shfl sum; rcp; store.
__global__ void __launch_bounds__(256, 4)
att_kernel(const float* __restrict__ adj, float* __restrict__ out) {
    __shared__ float  hs[kN * kPad];   // 64 rows of h[b,s,j,p,:]
    __shared__ float2 as2[8 * kN];     // (adj*log2e, 0.2*adj*log2e) per (i,j)

    const int tid  = threadIdx.x;
    const int warp = tid >> 5;
    const int lane = tid & 31;
    const int cg   = lane & 3;         // channel oct: c = 8*cg .. 8*cg+7
    const int grp  = lane >> 2;        // j subgroup (0..7)

    const int p  = blockIdx.x % kP;
    const int bs = blockIdx.x / kP;
    const int s  = bs & 3;
    const int b  = bs >> 2;
    const int i0 = (int)blockIdx.y * 8;
    const int i  = i0 + warp;

    // Stage h rows (512 float4); row j lives at +j*768 floats in g_h
    const float4* hb = (const float4*)(g_h + (b * 6144 + s * 1536 + p) * 32);
#pragma unroll
    for (int r = 0; r < 2; ++r) {
        int idx = tid + r * 256;            // 0..511
        int jj = idx >> 3, q = idx & 7;
        *(float4*)(hs + jj * kPad + q * 4) = __ldg(hb + jj * 192 + q);
    }
    // Stage pre-scaled adjacency for this block's 8 i's
#pragma unroll
    for (int r = 0; r < 2; ++r) {
        int idx = tid + r * 256;
        float a = __ldg(adj + (i0 + (idx >> 6)) * kN + (idx & 63)) * kLog2e;
        as2[idx] = make_float2(a, 0.2f * a);
    }
    __syncthreads();

    // h_i channels owned by this lane (8 floats)
    const float4 hiu = *(const float4*)(hs + i * kPad + cg * 8);
    const float4 hiv = *(const float4*)(hs + i * kPad + cg * 8 + 4);
    const float hi0 = hiu.x, hi1 = hiu.y, hi2 = hiu.z, hi3 = hiu.w;
    const float hi4 = hiv.x, hi5 = hiv.y, hi6 = hiv.z, hi7 = hiv.w;

    const int t = p * kNP + s;
    float* ob = out + (((long long)(b * kN + i) * kN) * kT + t) * kC + cg * 8;
    const float2* aw = as2 + warp * kN;

    float rs0 = 0.f, rs1 = 0.f, rs2 = 0.f, rs3 = 0.f;
    float rs4 = 0.f, rs5 = 0.f, rs6 = 0.f, rs7 = 0.f;
#pragma unroll
    for (int jg = 0; jg < 8; ++jg) {
        const int j = jg * 8 + grp;
        const float4 u = *(const float4*)(hs + j * kPad + cg * 8);
        const float4 v = *(const float4*)(hs + j * kPad + cg * 8 + 4);
        const float2 A = aw[j];

        float x0 = hi0 * u.x, x1 = hi1 * u.y, x2 = hi2 * u.z, x3 = hi3 * u.w;
        float x4 = hi4 * v.x, x5 = hi5 * v.y, x6 = hi6 * v.z, x7 = hi7 * v.w;
        float e0 = ex2f(fmaxf(x0 * A.x, x0 * A.y));
        float e1 = ex2f(fmaxf(x1 * A.x, x1 * A.y));
        float e2 = ex2f(fmaxf(x2 * A.x, x2 * A.y));
        float e3 = ex2f(fmaxf(x3 * A.x, x3 * A.y));
        float e4 = ex2f(fmaxf(x4 * A.x, x4 * A.y));
        float e5 = ex2f(fmaxf(x5 * A.x, x5 * A.y));
        float e6 = ex2f(fmaxf(x6 * A.x, x6 * A.y));
        float e7 = ex2f(fmaxf(x7 * A.x, x7 * A.y));

        float sl = ((e0 + e1) + (e2 + e3)) + ((e4 + e5) + (e6 + e7));
        sl += __shfl_xor_sync(0xffffffffu, sl, 1);
        sl += __shfl_xor_sync(0xffffffffu, sl, 2);
        const float inv = rcpf(sl);

        float o0 = e0 * inv, o1 = e1 * inv, o2 = e2 * inv, o3 = e3 * inv;
        float o4 = e4 * inv, o5 = e5 * inv, o6 = e6 * inv, o7 = e7 * inv;
        rs0 += o0; rs1 += o1; rs2 += o2; rs3 += o3;
        rs4 += o4; rs5 += o5; rs6 += o6; rs7 += o7;

        float* dst = ob + j * (kT * kC);
        *(float4*)dst       = make_float4(o0, o1, o2, o3);
        *(float4*)(dst + 4) = make_float4(o4, o5, o6, o7);
    }

    // Reduce rsum across the 8 j-subgroups (lane bits 2,3,4)
#pragma unroll
    for (int mask = 4; mask <= 16; mask <<= 1) {
        rs0 += __shfl_xor_sync(0xffffffffu, rs0, mask);
        rs1 += __shfl_xor_sync(0xffffffffu, rs1, mask);
        rs2 += __shfl_xor_sync(0xffffffffu, rs2, mask);
        rs3 += __shfl_xor_sync(0xffffffffu, rs3, mask);
        rs4 += __shfl_xor_sync(0xffffffffu, rs4, mask);
        rs5 += __shfl_xor_sync(0xffffffffu, rs5, mask);
        rs6 += __shfl_xor_sync(0xffffffffu, rs6, mask);
        rs7 += __shfl_xor_sync(0xffffffffu, rs7, mask);
    }

    if (grp == 0) {   // lanes 0..3 hold full sums for channels 8*cg..8*cg+7
        const int sh = t / kP, ph = t % kP;     // h_flat decomposition of t
        const float* hf = g_h + (b * 6144 + sh * 1536 + i * kP + ph) * 32 + cg * 8;
        const float4 hv0 = *(const float4*)hf;
        const float4 hv1 = *(const float4*)(hf + 4);
        float h0 = rs0 * hv0.x, h1 = rs1 * hv0.y;
        float h2 = rs2 * hv0.z, h3 = rs3 * hv0.w;
        float h4 = rs4 * hv1.x, h5 = rs5 * hv1.y;
        float h6 = rs6 * hv1.z, h7 = rs7 * hv1.w;
        float4 o0, o1;
        o0.x = h0 > 0.f ? h0 : expm1f(h0);
        o0.y = h1 > 0.f ? h1 : expm1f(h1);
        o0.z = h2 > 0.f ? h2 : expm1f(h2);
        o0.w = h3 > 0.f ? h3 : expm1f(h3);
        o1.x = h4 > 0.f ? h4 : expm1f(h4);
        o1.y = h5 > 0.f ? h5 : expm1f(h5);
        o1.z = h6 > 0.f ? h6 : expm1f(h6);
        o1.w = h7 > 0.f ? h7 : expm1f(h7);
        float* od = out + kAttElems +
                    ((long long)(b * kN + i) * kT + t) * kC + cg * 8;
        *(float4*)od       = o0;
        *(float4*)(od + 4) = o1;
    }
}

extern "C" void kernel_launch(void* const* d_in, const int* in_sizes, int n_in,
                              void* d_out, int out_size) {
    const float* x   = (const float*)d_in[0];
    const float* adj = (const float*)d_in[1];
    const float* W   = (const float*)d_in[2];
    float* out = (float*)d_out;

    h_kernel<<<(kRows * kC / 4) / 256, 256>>>(x, W);   // 384 blocks

    dim3 grid(kB * kNP * kP, kN / 8);   // (192, 8)
    att_kernel<<<grid, 256>>>(adj, out);
}

// round 7
// speedup vs baseline: 1.3089x; 1.3089x over previous
#include <cuda_runtime.h>

namespace {
constexpr int kB = 2, kNP = 4, kN = 64, kP = 24, kCin = 16, kC = 32, kT = 96;
constexpr int kRows = kB * kNP * kN * kP;                                // 12288
constexpr long long kAttElems = (long long)kB * kN * kN * kT * kC;       // 25165824
constexpr int kPad = 36;          // smem row stride (floats), 16B-aligned
constexpr float kLog2e = 1.4426950408889634f;
}

__device__ float g_h[kRows * kC];   // h = x @ W, (B*6144, 32) row-major

__device__ __forceinline__ float ex2f(float x) {
    float r; asm("ex2.approx.f32 %0, %1;" : "=f"(r) : "f"(x)); return r;
}
__device__ __forceinline__ float rcpf(float x) {
    float r; asm("rcp.approx.f32 %0, %1;" : "=f"(r) : "f"(x)); return r;
}

// Kernel 1: h = x @ W. One thread = one row x 4-channel quad.
__global__ void h_kernel(const float* __restrict__ x, const float* __restrict__ W) {
    int gid = blockIdx.x * 256 + threadIdx.x;   // 98304 threads
    int q = gid & 7;                            // channel quad (c = 4q..4q+3)
    int row = gid >> 3;
    const float4* xr = (const float4*)(x + row * kCin);
    const float4* Wq = (const float4*)W + q;    // quad of W row k is at k*8+q
    float4 a0 = __ldg(xr), a1 = __ldg(xr + 1), a2 = __ldg(xr + 2), a3 = __ldg(xr + 3);
    float4 acc = make_float4(0.f, 0.f, 0.f, 0.f);
#define FMA4(s, k) { float4 w = __ldg(Wq + (k) * 8); \
    acc.x = fmaf(s, w.x, acc.x); acc.y = fmaf(s, w.y, acc.y); \
    acc.z = fmaf(s, w.z, acc.z); acc.w = fmaf(s, w.w, acc.w); }
    FMA4(a0.x, 0)  FMA4(a0.y, 1)  FMA4(a0.z, 2)  FMA4(a0.w, 3)
    FMA4(a1.x, 4)  FMA4(a1.y, 5)  FMA4(a1.z, 6)  FMA4(a1.w, 7)
    FMA4(a2.x, 8)  FMA4(a2.y, 9)  FMA4(a2.z, 10) FMA4(a2.w, 11)
    FMA4(a3.x, 12) FMA4(a3.y, 13) FMA4(a3.z, 14) FMA4(a3.w, 15)
#undef FMA4
    *(float4*)(g_h + row * kC + q * 4) = acc;
}

// Kernel 2 (R4 layout): warp = (b,s,i,p); 8-lane group owns one j
// (4 j's per iter, 16 iters); lane owns 4 channels.
// Inner op: x=hi*hj; m=max(x, 0.2f*x)*a1; ex2; 3-stage shfl sum; rcp; store.
__global__ void __launch_bounds__(256, 6)
att_kernel(const float* __restrict__ adj, float* __restrict__ out) {
    __shared__ float hs[kN * kPad];   // 64 rows of h[b,s,j,p,:]
    __shared__ float as1[8 * kN];     // adj * log2e per (i,j)

    const int tid  = threadIdx.x;
    const int warp = tid >> 5;
    const int lane = tid & 31;
    const int lg   = lane & 7;         // channel group: c = 4*lg..4*lg+3
    const int grp  = lane >> 3;        // j subgroup within warp (0..3)

    const int p  = blockIdx.x % kP;
    const int bs = blockIdx.x / kP;
    const int s  = bs & 3;
    const int b  = bs >> 2;
    const int i0 = (int)blockIdx.y * 8;
    const int i  = i0 + warp;

    // Stage h rows (512 float4); row j lives at +j*768 floats in g_h
    const float4* hb = (const float4*)(g_h + (b * 6144 + s * 1536 + p) * 32);
#pragma unroll
    for (int r = 0; r < 2; ++r) {
        int idx = tid + r * 256;            // 0..511
        int jj = idx >> 3, q = idx & 7;
        *(float4*)(hs + jj * kPad + q * 4) = __ldg(hb + jj * 192 + q);
    }
    // Stage pre-scaled adjacency for this block's 8 i's
#pragma unroll
    for (int r = 0; r < 2; ++r) {
        int idx = tid + r * 256;
        as1[idx] = __ldg(adj + (i0 + (idx >> 6)) * kN + (idx & 63)) * kLog2e;
    }
    __syncthreads();

    // h_i channels owned by this lane
    const float4 hiv = *(const float4*)(hs + i * kPad + lg * 4);

    const int t = p * kNP + s;
    float* dst = out + (((long long)(b * kN + i) * kN + grp) * kT + t) * kC + lg * 4;
    const float* hrow = hs + grp * kPad + lg * 4;
    const float* aw   = as1 + warp * kN + grp;

    float rs0 = 0.f, rs1 = 0.f, rs2 = 0.f, rs3 = 0.f;
#pragma unroll
    for (int jg = 0; jg < 16; ++jg) {
        const float4 hj = *(const float4*)hrow;
        const float a1 = *aw;

        float x0 = hiv.x * hj.x, x1 = hiv.y * hj.y;
        float x2 = hiv.z * hj.z, x3 = hiv.w * hj.w;
        float m0 = fmaxf(x0, 0.2f * x0) * a1;
        float m1 = fmaxf(x1, 0.2f * x1) * a1;
        float m2 = fmaxf(x2, 0.2f * x2) * a1;
        float m3 = fmaxf(x3, 0.2f * x3) * a1;
        float e0 = ex2f(m0), e1 = ex2f(m1), e2 = ex2f(m2), e3 = ex2f(m3);

        float sl = (e0 + e1) + (e2 + e3);
        sl += __shfl_xor_sync(0xffffffffu, sl, 1);
        sl += __shfl_xor_sync(0xffffffffu, sl, 2);
        sl += __shfl_xor_sync(0xffffffffu, sl, 4);
        const float inv = rcpf(sl);

        float o0 = e0 * inv, o1 = e1 * inv, o2 = e2 * inv, o3 = e3 * inv;
        rs0 += o0; rs1 += o1; rs2 += o2; rs3 += o3;
        *(float4*)dst = make_float4(o0, o1, o2, o3);   // full 128B line per j

        dst  += 4 * kT * kC;     // next j for this subgroup
        hrow += 4 * kPad;
        aw   += 4;
    }

    // Reduce rsum across the 4 j-subgroups (lane bits 3,4)
    rs0 += __shfl_xor_sync(0xffffffffu, rs0, 8);
    rs1 += __shfl_xor_sync(0xffffffffu, rs1, 8);
    rs2 += __shfl_xor_sync(0xffffffffu, rs2, 8);
    rs3 += __shfl_xor_sync(0xffffffffu, rs3, 8);
    rs0 += __shfl_xor_sync(0xffffffffu, rs0, 16);
    rs1 += __shfl_xor_sync(0xffffffffu, rs1, 16);
    rs2 += __shfl_xor_sync(0xffffffffu, rs2, 16);
    rs3 += __shfl_xor_sync(0xffffffffu, rs3, 16);

    if (grp == 0) {   // lanes 0..7 hold full sums for channels 4*lg..4*lg+3
        const int sh = t / kP, ph = t % kP;     // h_flat decomposition of t
        const float4 hv = *(const float4*)(g_h +
            (b * 6144 + sh * 1536 + i * kP + ph) * 32 + lg * 4);
        float h0 = rs0 * hv.x, h1 = rs1 * hv.y, h2 = rs2 * hv.z, h3 = rs3 * hv.w;
        float4 r;
        r.x = h0 > 0.f ? h0 : expm1f(h0);
        r.y = h1 > 0.f ? h1 : expm1f(h1);
        r.z = h2 > 0.f ? h2 : expm1f(h2);
        r.w = h3 > 0.f ? h3 : expm1f(h3);
        *(float4*)(out + kAttElems +
                   ((long long)(b * kN + i) * kT + t) * kC + lg * 4) = r;
    }
}

extern "C" void kernel_launch(void* const* d_in, const int* in_sizes, int n_in,
                              void* d_out, int out_size) {
    const float* x   = (const float*)d_in[0];
    const float* adj = (const float*)d_in[1];
    const float* W   = (const float*)d_in[2];
    float* out = (float*)d_out;

    h_kernel<<<(kRows * kC / 4) / 256, 256>>>(x, W);   // 384 blocks

    dim3 grid(kB * kNP * kP, kN / 8);   // (192, 8)
    att_kernel<<<grid, 256>>>(adj, out);
}